// round 5
// baseline (speedup 1.0000x reference)
#include <cuda_runtime.h>
#include <math.h>

#define S_ 512
#define B_ 64
#define I_ 256
#define H_ 1024
#define L_ 3
#define BH_ (B_ * H_)      // 65536
#define LBH_ (L_ * BH_)    // 196608

#define N_PRE_ITEMS (S_ * 64)   // 32768: (s, colTile16) for X@W_xh
#define N_STEP_ITEMS 192        // 128 heavy (L1/L2 colTile16) + 64 light (L0 colTile16)

// -------- scratch (static device memory; no runtime allocation) --------
__device__ float g_P[(size_t)S_ * B_ * H_];   // precomputed X@W_xh + b_h
__device__ float g_h[2][LBH_];                // double-buffered hidden state
__device__ int g_ctr_pre;
__device__ int g_ctr[S_];
__device__ unsigned g_cnt;
__device__ volatile unsigned g_gen;

typedef unsigned long long ull;

__device__ __forceinline__ void ffma2(ull& d, ull a, ull b) {
    // packed 2xfp32 FMA: d = a*b + d  (element-wise on the two lanes)
    asm volatile("fma.rn.f32x2 %0, %1, %2, %0;" : "+l"(d) : "l"(a), "l"(b));
}
__device__ __forceinline__ float2 unpk(ull v) {
    float2 r;
    asm("mov.b64 {%0, %1}, %2;" : "=f"(r.x), "=f"(r.y) : "l"(v));
    return r;
}

// -------- software grid barrier (all blocks resident; grid = #SMs) --------
__device__ __forceinline__ void grid_sync(unsigned nb) {
    __syncthreads();
    if (threadIdx.x == 0) {
        __threadfence();                 // make this block's stores visible
        unsigned g = g_gen;
        if (atomicAdd(&g_cnt, 1u) == nb - 1u) {
            g_cnt = 0;
            __threadfence();
            g_gen = g + 1u;
        } else {
            while (g_gen == g) { }
        }
    }
    __syncthreads();
}

// -------- 64x16 output tile, K-loop GEMM core (fp32, FFMA2) --------
// A[b][k] = A + b*lda + k   (64 rows, read via ld.cg -> L2-fresh)
// W[k][c] = W + k*ldw + colbase + c  (immutable weights, ld.g/L1)
// Accumulates into a00,a01 (row r0; even-k / odd-k chains) and a10,a11 (row r1).
// SMEM layouts (padded stride 132 words -> bank-conflict-free LDS.128):
//   sh_h[b*132 + 2k + {0,1}] = A[b][k] duplicated  (FFMA2 "a" operand, no packing)
//   sh_w[(c/2)*132 + 2k + (c&1)] = W[k][c]          (FFMA2 "b" operand pairs)
__device__ __forceinline__ void load_chunk_regs(
    const float* __restrict__ A, int lda,
    const float* __restrict__ W, int ldw,
    int k0, int colbase, float hv[16], float wv[4])
{
    const int tid = threadIdx.x;
#pragma unroll
    for (int it = 0; it < 16; ++it) {
        int idx = tid + (it << 8);
        int b = idx >> 6, kk = idx & 63;
        hv[it] = __ldcg(A + b * lda + k0 + kk);
    }
#pragma unroll
    for (int it = 0; it < 4; ++it) {
        int idx = tid + (it << 8);
        int kk = idx >> 4, c = idx & 15;
        wv[it] = __ldg(&W[(size_t)(k0 + kk) * ldw + colbase + c]);
    }
}

__device__ __forceinline__ void mm64x16(
    const float* __restrict__ A, int lda,
    const float* __restrict__ W, int ldw,
    int K, int colbase,
    float* sh_h, float* sh_w,
    ull& a00, ull& a01, ull& a10, ull& a11)
{
    const int tid = threadIdx.x;
    const int warp = tid >> 5, lane = tid & 31;
    const int r0 = (warp << 2) + (lane >> 3);   // 0..31
    const int cp = lane & 7;                    // column pair 0..7

    const ulonglong2* hp0 = (const ulonglong2*)(sh_h + r0 * 132);
    const ulonglong2* hp1 = (const ulonglong2*)(sh_h + (r0 + 32) * 132);
    const ulonglong2* wp  = (const ulonglong2*)(sh_w + cp * 132);

    float hv[16], wv[4];
    load_chunk_regs(A, lda, W, ldw, 0, colbase, hv, wv);

    const int nch = K >> 6;     // KC = 64
    for (int ch = 0; ch < nch; ++ch) {
        __syncthreads();        // previous consumers of smem are done
        // registers -> smem (duplicated h, paired w)
        float2* shh2 = (float2*)sh_h;
#pragma unroll
        for (int it = 0; it < 16; ++it) {
            int idx = tid + (it << 8);
            int b = idx >> 6, kk = idx & 63;
            shh2[b * 66 + kk] = make_float2(hv[it], hv[it]);
        }
#pragma unroll
        for (int it = 0; it < 4; ++it) {
            int idx = tid + (it << 8);
            int kk = idx >> 4, c = idx & 15;
            sh_w[(c >> 1) * 132 + (kk << 1) + (c & 1)] = wv[it];
        }
        __syncthreads();
        if (ch + 1 < nch)       // prefetch next chunk (overlaps compute)
            load_chunk_regs(A, lda, W, ldw, (ch + 1) << 6, colbase, hv, wv);
        // compute 64 K-steps: per iter 3x LDS.128 + 4x FFMA2 (16 FMA)
#pragma unroll
        for (int kk2 = 0; kk2 < 32; ++kk2) {
            ulonglong2 h0 = hp0[kk2];
            ulonglong2 h1 = hp1[kk2];
            ulonglong2 w2 = wp[kk2];
            ffma2(a00, h0.x, w2.x);
            ffma2(a01, h0.y, w2.y);
            ffma2(a10, h1.x, w2.x);
            ffma2(a11, h1.y, w2.y);
        }
    }
}

// -------- persistent kernel: phase-0 precompute + 512 recurrent steps --------
__global__ void __launch_bounds__(256, 1) rnn_persistent(
    const float* __restrict__ X, const float* __restrict__ W_xh,
    const float* __restrict__ W_hh, const float* __restrict__ b_h,
    const float* __restrict__ W_layers, const float* __restrict__ U_layers,
    const float* __restrict__ b_layers, float* __restrict__ out,
    int nblocks, int out_size)
{
    __shared__ __align__(16) float sh_h[64 * 132];
    __shared__ __align__(16) float sh_w[8 * 132];
    __shared__ int s_item;

    const int tid = threadIdx.x;
    const int warp = tid >> 5, lane = tid & 31;
    const int r0 = (warp << 2) + (lane >> 3);
    const int r1 = r0 + 32;
    const int cp = lane & 7;
    const bool want_hfinal = (out_size >= (int)((size_t)S_ * BH_ + LBH_));

    // ---- phase 0: g_P = X @ W_xh + b_h ----
    for (;;) {
        if (tid == 0) s_item = atomicAdd(&g_ctr_pre, 1);
        __syncthreads();
        int t = s_item;
        if (t >= N_PRE_ITEMS) break;
        int s = t >> 6, colb = (t & 63) << 4;
        ull a00 = 0, a01 = 0, a10 = 0, a11 = 0;
        mm64x16(X + (size_t)s * B_ * I_, I_, W_xh, H_, I_, colb,
                sh_h, sh_w, a00, a01, a10, a11);
        int c = colb + (cp << 1);
        float bh0 = b_h[c], bh1 = b_h[c + 1];
        float2 u0 = unpk(a00), u1 = unpk(a01), v0 = unpk(a10), v1 = unpk(a11);
        float* Ps = g_P + (size_t)s * BH_;
        *(float2*)&Ps[r0 * H_ + c] = make_float2(u0.x + u1.x + bh0, u0.y + u1.y + bh1);
        *(float2*)&Ps[r1 * H_ + c] = make_float2(v0.x + v1.x + bh0, v0.y + v1.y + bh1);
    }
    grid_sync(nblocks);

    // ---- recurrence ----
    for (int s = 0; s < S_; ++s) {
        const float* hold = g_h[s & 1];
        float* hnew = g_h[(s & 1) ^ 1];
        for (;;) {
            if (tid == 0) s_item = atomicAdd(&g_ctr[s], 1);
            __syncthreads();
            int t = s_item;
            if (t >= N_STEP_ITEMS) break;
            // heavy items (layers 1..2, cost 2) first for greedy balance
            int layer, ct;
            if (t < 128) { layer = 1 + (t & 1); ct = t >> 1; }
            else         { layer = 0;           ct = t - 128; }
            int colb = ct << 4;
            ull a00 = 0, a01 = 0, a10 = 0, a11 = 0;
            if (layer == 0) {
                mm64x16(hold, H_, W_hh, H_, H_, colb, sh_h, sh_w, a00, a01, a10, a11);
            } else {
                const float* Um = U_layers + (size_t)(layer - 1) * H_ * H_;
                const float* Wm = W_layers + (size_t)(layer - 1) * H_ * H_;
                mm64x16(hold + (size_t)layer * BH_,       H_, Um, H_, H_, colb,
                        sh_h, sh_w, a00, a01, a10, a11);
                mm64x16(hold + (size_t)(layer - 1) * BH_, H_, Wm, H_, H_, colb,
                        sh_h, sh_w, a00, a01, a10, a11);
            }
            int c = colb + (cp << 1);
            float2 u0 = unpk(a00), u1 = unpk(a01), v0 = unpk(a10), v1 = unpk(a11);
            float p00, p01, p10, p11;
            if (layer == 0) {
                const float* Ps = g_P + (size_t)s * BH_;
                float2 q0 = *(const float2*)&Ps[r0 * H_ + c];
                float2 q1 = *(const float2*)&Ps[r1 * H_ + c];
                p00 = q0.x; p01 = q0.y; p10 = q1.x; p11 = q1.y;
            } else {
                float bb0 = b_layers[(layer - 1) * H_ + c];
                float bb1 = b_layers[(layer - 1) * H_ + c + 1];
                p00 = bb0; p01 = bb1; p10 = bb0; p11 = bb1;
            }
            float o00 = tanhf(u0.x + u1.x + p00);
            float o01 = tanhf(u0.y + u1.y + p01);
            float o10 = tanhf(v0.x + v1.x + p10);
            float o11 = tanhf(v0.y + v1.y + p11);

            float* hn = hnew + (size_t)layer * BH_;
            __stcg((float2*)&hn[r0 * H_ + c], make_float2(o00, o01));
            __stcg((float2*)&hn[r1 * H_ + c], make_float2(o10, o11));
            if (layer == 2) {
                float* os = out + (size_t)s * BH_;
                *(float2*)&os[r0 * H_ + c] = make_float2(o00, o01);
                *(float2*)&os[r1 * H_ + c] = make_float2(o10, o11);
            }
            if (s == S_ - 1 && want_hfinal) {
                float* hf = out + (size_t)S_ * BH_ + (size_t)layer * BH_;
                *(float2*)&hf[r0 * H_ + c] = make_float2(o00, o01);
                *(float2*)&hf[r1 * H_ + c] = make_float2(o10, o11);
            }
        }
        grid_sync(nblocks);
    }
}

__global__ void rnn_init() {
    int idx = blockIdx.x * blockDim.x + threadIdx.x;
    int stride = gridDim.x * blockDim.x;
    if (idx == 0) g_ctr_pre = 0;
    if (idx < S_) g_ctr[idx] = 0;
    for (int i = idx; i < LBH_; i += stride) g_h[0][i] = 0.0f;
}

extern "C" void kernel_launch(void* const* d_in, const int* in_sizes, int n_in,
                              void* d_out, int out_size) {
    const float* X    = (const float*)d_in[0];
    const float* W_xh = (const float*)d_in[1];
    const float* W_hh = (const float*)d_in[2];
    const float* b_h  = (const float*)d_in[3];
    const float* W_l  = (const float*)d_in[4];
    const float* U_l  = (const float*)d_in[5];
    const float* b_l  = (const float*)d_in[6];
    float* out = (float*)d_out;

    int nsm = 148;
    cudaDeviceGetAttribute(&nsm, cudaDevAttrMultiProcessorCount, 0);
    if (nsm < 1) nsm = 148;
    if (nsm > 512) nsm = 512;

    rnn_init<<<256, 256>>>();
    rnn_persistent<<<nsm, 256>>>(X, W_xh, W_hh, b_h, W_l, U_l, b_l, out,
                                 nsm, out_size);
}

// round 8
// speedup vs baseline: 2.1896x; 2.1896x over previous
#include <cuda_runtime.h>
#include <cuda_bf16.h>
#include <math.h>
#include <stdint.h>

#define S_ 512
#define B_ 64
#define I_ 256
#define H_ 1024
#define BH_ 65536
#define LBH_ 196608
#define NB 80

// ---------------- static device scratch ----------------
__device__ __align__(16) float g_P[(size_t)S_ * BH_];
__device__ __align__(16) __nv_bfloat16 g_Whi[2688 * 2048];   // 5 mats + Wxh, blocked
__device__ __align__(16) __nv_bfloat16 g_Wlo[2688 * 2048];
__device__ __align__(16) __nv_bfloat16 g_Xhi[8192 * 1024];
__device__ __align__(16) __nv_bfloat16 g_Xlo[8192 * 1024];
__device__ __align__(16) __nv_bfloat16 g_hhi[2 * LBH_];      // double-buffered
__device__ __align__(16) __nv_bfloat16 g_hlo[2 * LBH_];
__device__ __align__(16) float g_part[NB * 8192];
__device__ unsigned g_flag[64];
__device__ unsigned g_cnt;
__device__ volatile unsigned g_gen;

// element index inside a blocked row: row r (feature or batch), j = k&15.
// XOR swizzle on the 4B-word index kills the 2-way LDS bank conflict.
__device__ __forceinline__ uint32_t rowoff(int r, int j) {
    int w = j >> 1;
    return (uint32_t)(r * 16 + (((w ^ (r & 4)) << 1) | (j & 1)));
}

// ---------------- PTX helpers ----------------
__device__ __forceinline__ uint32_t smem_u32(const void* p) {
    uint32_t a;
    asm("{ .reg .u64 t; cvta.to.shared.u64 t, %1; cvt.u32.u64 %0, t; }" : "=r"(a) : "l"(p));
    return a;
}
__device__ __forceinline__ void cp16(uint32_t s, const void* g) {
    asm volatile("cp.async.cg.shared.global [%0], [%1], 16;" :: "r"(s), "l"(g) : "memory");
}
__device__ __forceinline__ void cp_commit() { asm volatile("cp.async.commit_group;" ::: "memory"); }
__device__ __forceinline__ void cp_wait2()  { asm volatile("cp.async.wait_group 2;" ::: "memory"); }

__device__ __forceinline__ void mma16816(float* d, uint32_t a0, uint32_t a1, uint32_t a2,
                                         uint32_t a3, uint32_t b0, uint32_t b1) {
    asm volatile(
        "mma.sync.aligned.m16n8k16.row.col.f32.bf16.bf16.f32 "
        "{%0,%1,%2,%3}, {%4,%5,%6,%7}, {%8,%9}, {%0,%1,%2,%3};"
        : "+f"(d[0]), "+f"(d[1]), "+f"(d[2]), "+f"(d[3])
        : "r"(a0), "r"(a1), "r"(a2), "r"(a3), "r"(b0), "r"(b1));
}

__device__ __forceinline__ void grid_sync(unsigned nb) {
    __syncthreads();
    if (threadIdx.x == 0) {
        __threadfence();
        unsigned g = g_gen;
        if (atomicAdd(&g_cnt, 1u) == nb - 1u) {
            g_cnt = 0;
            __threadfence();
            g_gen = g + 1u;
        } else {
            while (g_gen == g) { }
        }
    }
    __syncthreads();
}

// ---------------- prep kernels ----------------
__global__ void k_init() {
    int i = blockIdx.x * blockDim.x + threadIdx.x;
    uint32_t* a = (uint32_t*)g_hhi;
    uint32_t* b = (uint32_t*)g_hlo;
    if (i < 196608) { a[i] = 0u; b[i] = 0u; }
    if (i < 64) g_flag[i] = 0u;
}
__device__ __forceinline__ void wsplit(float v, size_t e) {
    __nv_bfloat16 hi = __float2bfloat16(v);
    g_Whi[e] = hi;
    g_Wlo[e] = __float2bfloat16(v - __bfloat162float(hi));
}
__global__ void k_prepw(const float* __restrict__ Whh, const float* __restrict__ Wl,
                        const float* __restrict__ Ul) {
    int idx = blockIdx.x * blockDim.x + threadIdx.x;
    if (idx >= 5 * 1024 * 1024) return;
    int g = idx >> 20, rem = idx & 1048575, k = rem >> 10, f = rem & 1023;
    float v;
    if (g == 0)      v = Whh[(size_t)k * H_ + f];
    else if (g == 1) v = Ul[(size_t)k * H_ + f];
    else if (g == 2) v = Wl[(size_t)k * H_ + f];
    else if (g == 3) v = Ul[(size_t)H_ * H_ + (size_t)k * H_ + f];
    else             v = Wl[(size_t)H_ * H_ + (size_t)k * H_ + f];
    size_t blk = (size_t)(g * 8 + (f >> 7)) * 64 + (k >> 4);
    wsplit(v, blk * 2048 + rowoff(f & 127, k & 15));
}
__global__ void k_prepxh(const float* __restrict__ Wxh) {
    int idx = blockIdx.x * blockDim.x + threadIdx.x;
    if (idx >= 256 * 1024) return;
    int k = idx >> 10, f = idx & 1023;
    size_t blk = 2560 + (size_t)(f >> 7) * 16 + (k >> 4);
    wsplit(Wxh[(size_t)k * H_ + f], blk * 2048 + rowoff(f & 127, k & 15));
}
__global__ void k_prepx(const float* __restrict__ X) {
    int idx = blockIdx.x * blockDim.x + threadIdx.x;
    if (idx >= S_ * B_ * I_) return;
    int s = idx >> 14, b = (idx >> 8) & 63, i = idx & 255;
    float v = X[idx];
    size_t e = ((size_t)s * 16 + (i >> 4)) * 1024 + rowoff(b, i & 15);
    __nv_bfloat16 hi = __float2bfloat16(v);
    g_Xhi[e] = hi;
    g_Xlo[e] = __float2bfloat16(v - __bfloat162float(hi));
}

// ---------------- GEMM core ----------------
__device__ __forceinline__ void load_chunk(uint32_t sbase, int slot,
                                           const char* Ah, const char* Al,
                                           const char* Bh, const char* Bl,
                                           int c, int tid) {
    uint32_t so = sbase + slot * 12288;
    cp16(so + tid * 16, Ah + (size_t)c * 4096 + tid * 16);
    cp16(so + 4096 + tid * 16, Al + (size_t)c * 4096 + tid * 16);
    if (tid < 128) cp16(so + 8192 + tid * 16, Bh + (size_t)c * 2048 + tid * 16);
    else           cp16(so + 10240 + (tid - 128) * 16, Bl + (size_t)c * 2048 + (tid - 128) * 16);
}

__device__ __forceinline__ void compute_iter(const char* sm, int slot, int wid, int lane,
                                             float d[2][4][4]) {
    const int g = lane >> 2, t = lane & 3;
    const int fr = (wid >> 1) * 32, nb = (wid & 1) * 32;
    const int sw = g & 4;
    const char* A = sm + slot * 12288;
    const char* B = A + 8192;
    uint32_t ah[2][4], al[2][4], bh[4][2], bl[4][2];
#pragma unroll
    for (int mt = 0; mt < 2; ++mt) {
        int r0 = fr + mt * 16 + g;
        uint32_t o0 = (uint32_t)(r0 * 32 + ((t ^ sw) << 2));
        uint32_t o2 = (uint32_t)(r0 * 32 + (((t + 4) ^ sw) << 2));
        ah[mt][0] = *(const uint32_t*)(A + o0);
        ah[mt][1] = *(const uint32_t*)(A + o0 + 256);
        ah[mt][2] = *(const uint32_t*)(A + o2);
        ah[mt][3] = *(const uint32_t*)(A + o2 + 256);
        al[mt][0] = *(const uint32_t*)(A + 4096 + o0);
        al[mt][1] = *(const uint32_t*)(A + 4096 + o0 + 256);
        al[mt][2] = *(const uint32_t*)(A + 4096 + o2);
        al[mt][3] = *(const uint32_t*)(A + 4096 + o2 + 256);
    }
#pragma unroll
    for (int nt = 0; nt < 4; ++nt) {
        int rb = nb + nt * 8 + g;
        uint32_t o0 = (uint32_t)(rb * 32 + ((t ^ sw) << 2));
        uint32_t o1 = (uint32_t)(rb * 32 + (((t + 4) ^ sw) << 2));
        bh[nt][0] = *(const uint32_t*)(B + o0);
        bh[nt][1] = *(const uint32_t*)(B + o1);
        bl[nt][0] = *(const uint32_t*)(B + 2048 + o0);
        bl[nt][1] = *(const uint32_t*)(B + 2048 + o1);
    }
#pragma unroll
    for (int mt = 0; mt < 2; ++mt)
#pragma unroll
        for (int nt = 0; nt < 4; ++nt) {
            mma16816(d[mt][nt], ah[mt][0], ah[mt][1], ah[mt][2], ah[mt][3], bh[nt][0], bh[nt][1]);
            mma16816(d[mt][nt], al[mt][0], al[mt][1], al[mt][2], al[mt][3], bh[nt][0], bh[nt][1]);
            mma16816(d[mt][nt], ah[mt][0], ah[mt][1], ah[mt][2], ah[mt][3], bl[nt][0], bl[nt][1]);
        }
}

template <int NCH>
__device__ __forceinline__ void gemm_pipe(const char* Ah, const char* Al,
                                          const char* Bh, const char* Bl,
                                          const char* sm, uint32_t sbase,
                                          float d[2][4][4], int tid, int wid, int lane) {
#pragma unroll
    for (int c = 0; c < 3; ++c) {
        if (c < NCH) load_chunk(sbase, c, Ah, Al, Bh, Bl, c, tid);
        cp_commit();
    }
#pragma unroll 4
    for (int c = 0; c < NCH; ++c) {
        cp_wait2();
        __syncthreads();
        if (c + 3 < NCH) load_chunk(sbase, (c + 3) & 3, Ah, Al, Bh, Bl, c + 3, tid);
        cp_commit();
        compute_iter(sm, c & 3, wid, lane, d);
    }
}

__device__ __forceinline__ void stage_D(char* sm, float d[2][4][4], int wid, int lane) {
    float* st = (float*)sm;
    const int g = lane >> 2, t = lane & 3;
    const int fr = (wid >> 1) * 32, nb = (wid & 1) * 32;
#pragma unroll
    for (int mt = 0; mt < 2; ++mt)
#pragma unroll
        for (int nt = 0; nt < 4; ++nt) {
            int f0 = fr + mt * 16 + g, b0 = nb + nt * 8 + 2 * t;
            st[b0 * 132 + f0]           = d[mt][nt][0];
            st[(b0 + 1) * 132 + f0]     = d[mt][nt][1];
            st[b0 * 132 + f0 + 8]       = d[mt][nt][2];
            st[(b0 + 1) * 132 + f0 + 8] = d[mt][nt][3];
        }
}

// ---------------- main persistent kernel ----------------
__global__ void __launch_bounds__(256) k_main(const float* __restrict__ b_h,
                                              const float* __restrict__ bL,
                                              float* __restrict__ out, int out_size) {
    __shared__ __align__(16) char smem[49152];
    const int tid = threadIdx.x;
    const int wid = tid >> 5, lane = tid & 31;
    const uint32_t sbase = smem_u32(smem);
    const int bid = blockIdx.x;
    const bool want_hf = (out_size >= (int)((size_t)S_ * BH_ + LBH_));
    float d[2][4][4];

    // ---- phase A: P = X @ W_xh + b_h ----
    for (int u = bid; u < 4096; u += NB) {
        int s = u >> 3, m = u & 7;
#pragma unroll
        for (int a = 0; a < 2; ++a)
            for (int b = 0; b < 4; ++b)
                for (int c = 0; c < 4; ++c) d[a][b][c] = 0.0f;
        const char* Ah = (const char*)g_Whi + ((size_t)2560 + m * 16) * 4096;
        const char* Al = (const char*)g_Wlo + ((size_t)2560 + m * 16) * 4096;
        const char* Bh = (const char*)g_Xhi + ((size_t)s * 16) * 2048;
        const char* Bl = (const char*)g_Xlo + ((size_t)s * 16) * 2048;
        gemm_pipe<16>(Ah, Al, Bh, Bl, smem, sbase, d, tid, wid, lane);
        __syncthreads();
        stage_D(smem, d, wid, lane);
        __syncthreads();
        {
            int b = tid >> 2, seg = tid & 3;
            float* Ps = g_P + (size_t)s * BH_ + (size_t)b * H_ + m * 128;
            const float* st = (const float*)smem;
#pragma unroll
            for (int i = 0; i < 8; ++i) {
                int f = (seg + 4 * i) * 4;
                float4 v = *(const float4*)(st + b * 132 + f);
                float4 bb = *(const float4*)(b_h + m * 128 + f);
                v.x += bb.x; v.y += bb.y; v.z += bb.z; v.w += bb.w;
                *(float4*)(Ps + f) = v;
            }
        }
        __syncthreads();
    }
    grid_sync(NB);

    // ---- phase B: recurrence ----
    int layer, m, kh, gs, unit;
    if (bid < 16) { layer = 0; m = bid >> 1; kh = bid & 1; gs = 2; unit = bid >> 1; }
    else {
        int i = bid - 16;
        layer = 1 + (i >> 5);
        m = (i & 31) >> 2;
        kh = i & 3;
        gs = 4;
        unit = 8 + (i >> 2);
    }
    int gmat, srcL, kb;
    if (layer == 0) { gmat = 0; srcL = 0; kb = kh * 32; }
    else if (kh < 2) { gmat = (layer == 1) ? 1 : 3; srcL = layer;     kb = kh * 32; }
    else             { gmat = (layer == 1) ? 2 : 4; srcL = layer - 1; kb = (kh - 2) * 32; }
    const bool leader = (kh == 0);
    const size_t ablk = ((size_t)(gmat * 8 + m) * 64 + kb) * 4096;
    const char* Ah = (const char*)g_Whi + ablk;
    const char* Al = (const char*)g_Wlo + ablk;
    const size_t hblk = ((size_t)srcL * 64 + kb) * 2048;

    for (int s = 0; s < S_; ++s) {
        const size_t rd = (size_t)(s & 1) * LBH_ * 2;        // byte offset
        const size_t wrE = (size_t)((s & 1) ^ 1) * LBH_;     // element offset
        const char* Bh = (const char*)g_hhi + rd + hblk;
        const char* Bl = (const char*)g_hlo + rd + hblk;
#pragma unroll
        for (int a = 0; a < 2; ++a)
            for (int b = 0; b < 4; ++b)
                for (int c = 0; c < 4; ++c) d[a][b][c] = 0.0f;
        gemm_pipe<32>(Ah, Al, Bh, Bl, smem, sbase, d, tid, wid, lane);
        __syncthreads();
        stage_D(smem, d, wid, lane);
        __syncthreads();
        {
            int b = tid >> 2, seg = tid & 3;
            float* pp = g_part + (size_t)bid * 8192 + b * 128;
            const float* st = (const float*)smem;
#pragma unroll
            for (int i = 0; i < 8; ++i) {
                int f = (seg + 4 * i) * 4;
                *(float4*)(pp + f) = *(const float4*)(st + b * 132 + f);
            }
        }
        __threadfence();
        __syncthreads();
        if (!leader) {
            if (tid == 0) atomicAdd(&g_flag[unit], 1u);
        } else {
            if (tid == 0) {
                unsigned tgt = (unsigned)(s + 1) * (unsigned)(gs - 1);
                while (*((volatile unsigned*)&g_flag[unit]) < tgt) { }
            }
            __syncthreads();
            __threadfence();
            // epilogue: combine partials, tanh, write h(+out)
            int f = tid & 127, half = tid >> 7;
            int mf = m * 128 + f;
            const float* p0 = g_part + (size_t)bid * 8192;
            float bias = (layer == 0) ? 0.0f : bL[(layer - 1) * H_ + mf];
            const float* Ps = g_P + (size_t)s * BH_;
            __nv_bfloat16* dh = g_hhi + wrE + ((size_t)layer * 64 + (mf >> 4)) * 1024;
            __nv_bfloat16* dl = g_hlo + wrE + ((size_t)layer * 64 + (mf >> 4)) * 1024;
            float* os = out + (size_t)s * BH_;
            for (int b = half * 32; b < half * 32 + 32; ++b) {
                float v = bias;
#pragma unroll
                for (int j = 0; j < 4; ++j)
                    if (j < gs) v += p0[(size_t)j * 8192 + b * 128 + f];
                if (layer == 0) v += Ps[(size_t)b * H_ + mf];
                float o = tanhf(v);
                __nv_bfloat16 hi = __float2bfloat16(o);
                uint32_t ro = rowoff(b, mf & 15) - (size_t)b * 16 + b * 16; // = rowoff(b, mf&15)
                dh[rowoff(b, mf & 15)] = hi;
                dl[rowoff(b, mf & 15)] = __float2bfloat16(o - __bfloat162float(hi));
                (void)ro;
                if (layer == 2) os[(size_t)b * H_ + mf] = o;
                if (s == S_ - 1 && want_hf)
                    out[(size_t)S_ * BH_ + (size_t)layer * BH_ + (size_t)b * H_ + mf] = o;
            }
        }
        grid_sync(NB);
    }
}

extern "C" void kernel_launch(void* const* d_in, const int* in_sizes, int n_in,
                              void* d_out, int out_size) {
    const float* X    = (const float*)d_in[0];
    const float* W_xh = (const float*)d_in[1];
    const float* W_hh = (const float*)d_in[2];
    const float* b_h  = (const float*)d_in[3];
    const float* W_l  = (const float*)d_in[4];
    const float* U_l  = (const float*)d_in[5];
    const float* b_l  = (const float*)d_in[6];
    float* out = (float*)d_out;

    k_init<<<768, 256>>>();
    k_prepw<<<20480, 256>>>(W_hh, W_l, U_l);
    k_prepxh<<<1024, 256>>>(W_xh);
    k_prepx<<<32768, 256>>>(X);
    k_main<<<NB, 256>>>(b_h, b_l, out, out_size);
}

// round 9
// speedup vs baseline: 4.9998x; 2.2834x over previous
#include <cuda_runtime.h>
#include <cuda_fp16.h>
#include <math.h>
#include <stdint.h>

#define S_ 512
#define B_ 64
#define I_ 256
#define H_ 1024
#define BH_ 65536
#define LBH_ 196608
#define NB 120
#define SLOT 20480
#define SMEM_DYN 81920
#define LOSCALE 2048.0f
#define ILOSCALE (1.0f / 2048.0f)

// ---------------- static device scratch ----------------
__device__ __align__(16) float g_P[(size_t)S_ * BH_];
__device__ __align__(16) __half g_Whi[2688 * 2048];   // 5 mats (64 K16-blocks) + Wxh (16 blocks) x 8 mtiles
__device__ __align__(16) __half g_Wlo[2688 * 2048];   // lo plane, pre-scaled by 2^11
__device__ __align__(16) __half g_Xf[8192 * 1024];    // X single fp16, blocked
__device__ __align__(16) __half g_hf[2 * LBH_];       // h single fp16, double-buffered
__device__ __align__(16) float g_part[NB * 8192];
__device__ unsigned g_flag[24];
__device__ unsigned g_cnt;
__device__ volatile unsigned g_gen;

// blocked-row element index with XOR swizzle (bank-conflict-free fragment loads)
__device__ __forceinline__ uint32_t rowoff(int r, int j) {
    int w = j >> 1;
    return (uint32_t)(r * 16 + (((w ^ (r & 4)) << 1) | (j & 1)));
}

// ---------------- PTX helpers ----------------
__device__ __forceinline__ uint32_t smem_u32(const void* p) {
    uint32_t a;
    asm("{ .reg .u64 t; cvta.to.shared.u64 t, %1; cvt.u32.u64 %0, t; }" : "=r"(a) : "l"(p));
    return a;
}
__device__ __forceinline__ void cp16(uint32_t s, const void* g) {
    asm volatile("cp.async.cg.shared.global [%0], [%1], 16;" :: "r"(s), "l"(g) : "memory");
}
__device__ __forceinline__ void cp_commit() { asm volatile("cp.async.commit_group;" ::: "memory"); }
__device__ __forceinline__ void cp_wait2()  { asm volatile("cp.async.wait_group 2;" ::: "memory"); }
__device__ __forceinline__ void cp_wait0()  { asm volatile("cp.async.wait_group 0;" ::: "memory"); }

__device__ __forceinline__ void mmaf16(float* d, uint32_t a0, uint32_t a1, uint32_t a2,
                                       uint32_t a3, uint32_t b0, uint32_t b1) {
    asm volatile(
        "mma.sync.aligned.m16n8k16.row.col.f32.f16.f16.f32 "
        "{%0,%1,%2,%3}, {%4,%5,%6,%7}, {%8,%9}, {%0,%1,%2,%3};"
        : "+f"(d[0]), "+f"(d[1]), "+f"(d[2]), "+f"(d[3])
        : "r"(a0), "r"(a1), "r"(a2), "r"(a3), "r"(b0), "r"(b1));
}

__device__ __forceinline__ void grid_sync(unsigned nb) {
    __syncthreads();
    if (threadIdx.x == 0) {
        __threadfence();
        unsigned g = g_gen;
        if (atomicAdd(&g_cnt, 1u) == nb - 1u) {
            g_cnt = 0;
            __threadfence();
            g_gen = g + 1u;
        } else {
            while (g_gen == g) { }
        }
    }
    __syncthreads();
}

// ---------------- prep kernels ----------------
__global__ void k_init() {
    int i = blockIdx.x * blockDim.x + threadIdx.x;
    uint32_t* a = (uint32_t*)g_hf;
    if (i < 196608) a[i] = 0u;
    if (i < 24) g_flag[i] = 0u;
}
__device__ __forceinline__ void wsplit(float v, size_t e) {
    __half hi = __float2half(v);
    g_Whi[e] = hi;
    g_Wlo[e] = __float2half((v - __half2float(hi)) * LOSCALE);
}
__global__ void k_prepw(const float* __restrict__ Whh, const float* __restrict__ Wl,
                        const float* __restrict__ Ul) {
    int idx = blockIdx.x * blockDim.x + threadIdx.x;
    if (idx >= 5 * 1024 * 1024) return;
    int g = idx >> 20, rem = idx & 1048575, k = rem >> 10, f = rem & 1023;
    float v;
    if (g == 0)      v = Whh[(size_t)k * H_ + f];
    else if (g == 1) v = Ul[(size_t)k * H_ + f];
    else if (g == 2) v = Wl[(size_t)k * H_ + f];
    else if (g == 3) v = Ul[(size_t)H_ * H_ + (size_t)k * H_ + f];
    else             v = Wl[(size_t)H_ * H_ + (size_t)k * H_ + f];
    size_t blk = (size_t)(g * 8 + (f >> 7)) * 64 + (k >> 4);
    wsplit(v, blk * 2048 + rowoff(f & 127, k & 15));
}
__global__ void k_prepxh(const float* __restrict__ Wxh) {
    int idx = blockIdx.x * blockDim.x + threadIdx.x;
    if (idx >= 256 * 1024) return;
    int k = idx >> 10, f = idx & 1023;
    size_t blk = 2560 + (size_t)(f >> 7) * 16 + (k >> 4);
    wsplit(Wxh[(size_t)k * H_ + f], blk * 2048 + rowoff(f & 127, k & 15));
}
__global__ void k_prepx(const float* __restrict__ X) {
    int idx = blockIdx.x * blockDim.x + threadIdx.x;
    if (idx >= S_ * B_ * I_) return;
    int s = idx >> 14, b = (idx >> 8) & 63, i = idx & 255;
    g_Xf[((size_t)s * 16 + (i >> 4)) * 1024 + rowoff(b, i & 15)] = __float2half(X[idx]);
}

// ---------------- GEMM core ----------------
__device__ __forceinline__ void load_chunk(uint32_t so, const char* Ah, const char* Al,
                                           const char* Bf, int c, int tid) {
    size_t ao = (size_t)c * 8192 + tid * 16;
    cp16(so + tid * 16, Ah + ao);
    cp16(so + 4096 + tid * 16, Ah + ao + 4096);
    cp16(so + 8192 + tid * 16, Al + ao);
    cp16(so + 12288 + tid * 16, Al + ao + 4096);
    cp16(so + 16384 + tid * 16, Bf + (size_t)c * 4096 + tid * 16);
}

__device__ __forceinline__ void sub_iter(const char* Ah, const char* Al, const char* Bf,
                                         int wid, int lane, float dh[2][4][4], float dl[2][4][4]) {
    const int g = lane >> 2, t = lane & 3;
    const int fr = (wid >> 1) * 32, nb = (wid & 1) * 32;
    const int sw = g & 4;
    uint32_t ah[2][4], al[2][4], bb[4][2];
#pragma unroll
    for (int mt = 0; mt < 2; ++mt) {
        int r0 = fr + mt * 16 + g;
        uint32_t o0 = (uint32_t)(r0 * 32 + ((t ^ sw) << 2));
        uint32_t o2 = (uint32_t)(r0 * 32 + (((t + 4) ^ sw) << 2));
        ah[mt][0] = *(const uint32_t*)(Ah + o0);
        ah[mt][1] = *(const uint32_t*)(Ah + o0 + 256);
        ah[mt][2] = *(const uint32_t*)(Ah + o2);
        ah[mt][3] = *(const uint32_t*)(Ah + o2 + 256);
        al[mt][0] = *(const uint32_t*)(Al + o0);
        al[mt][1] = *(const uint32_t*)(Al + o0 + 256);
        al[mt][2] = *(const uint32_t*)(Al + o2);
        al[mt][3] = *(const uint32_t*)(Al + o2 + 256);
    }
#pragma unroll
    for (int nt = 0; nt < 4; ++nt) {
        int rb = nb + nt * 8 + g;
        uint32_t o0 = (uint32_t)(rb * 32 + ((t ^ sw) << 2));
        uint32_t o1 = (uint32_t)(rb * 32 + (((t + 4) ^ sw) << 2));
        bb[nt][0] = *(const uint32_t*)(Bf + o0);
        bb[nt][1] = *(const uint32_t*)(Bf + o1);
    }
#pragma unroll
    for (int mt = 0; mt < 2; ++mt)
#pragma unroll
        for (int nt = 0; nt < 4; ++nt) {
            mmaf16(dh[mt][nt], ah[mt][0], ah[mt][1], ah[mt][2], ah[mt][3], bb[nt][0], bb[nt][1]);
            mmaf16(dl[mt][nt], al[mt][0], al[mt][1], al[mt][2], al[mt][3], bb[nt][0], bb[nt][1]);
        }
}

__device__ __forceinline__ void gemm_pipe(const char* Ah, const char* Al, const char* Bf,
                                          const char* sm, uint32_t sbase, int c0, int c1,
                                          float dh[2][4][4], float dl[2][4][4],
                                          int tid, int wid, int lane) {
#pragma unroll
    for (int i = 0; i < 3; ++i) {
        load_chunk(sbase + i * SLOT, Ah, Al, Bf, c0 + i, tid);
        cp_commit();
    }
    for (int c = c0; c < c1; ++c) {
        const int slot = (c - c0) & 3;
        cp_wait2();
        __syncthreads();
        if (c + 3 < c1) load_chunk(sbase + (((c - c0) + 3) & 3) * SLOT, Ah, Al, Bf, c + 3, tid);
        cp_commit();
        const char* p = sm + slot * SLOT;
        sub_iter(p, p + 8192, p + 16384, wid, lane, dh, dl);
        sub_iter(p + 4096, p + 12288, p + 18432, wid, lane, dh, dl);
    }
    cp_wait0();
    __syncthreads();
}

__device__ __forceinline__ void stage_D(char* sm, float dh[2][4][4], float dl[2][4][4],
                                        int wid, int lane) {
    float* st = (float*)sm;
    const int g = lane >> 2, t = lane & 3;
    const int fr = (wid >> 1) * 32, nb = (wid & 1) * 32;
#pragma unroll
    for (int mt = 0; mt < 2; ++mt)
#pragma unroll
        for (int nt = 0; nt < 4; ++nt) {
            int f0 = fr + mt * 16 + g, b0 = nb + nt * 8 + 2 * t;
            st[b0 * 132 + f0]           = dh[mt][nt][0] + dl[mt][nt][0] * ILOSCALE;
            st[(b0 + 1) * 132 + f0]     = dh[mt][nt][1] + dl[mt][nt][1] * ILOSCALE;
            st[b0 * 132 + f0 + 8]       = dh[mt][nt][2] + dl[mt][nt][2] * ILOSCALE;
            st[(b0 + 1) * 132 + f0 + 8] = dh[mt][nt][3] + dl[mt][nt][3] * ILOSCALE;
        }
}

#define ZACC()                                        \
    do {                                              \
        _Pragma("unroll") for (int a_ = 0; a_ < 2; ++a_) \
        _Pragma("unroll") for (int b_ = 0; b_ < 4; ++b_) \
        _Pragma("unroll") for (int c_ = 0; c_ < 4; ++c_) \
        { dh[a_][b_][c_] = 0.0f; dl[a_][b_][c_] = 0.0f; } \
    } while (0)

// ---------------- main persistent kernel (120 CTAs) ----------------
__global__ void __launch_bounds__(256, 1) k_main(const float* __restrict__ b_h,
                                                 const float* __restrict__ bL,
                                                 float* __restrict__ out, int out_size) {
    extern __shared__ __align__(16) char smem[];
    const int tid = threadIdx.x;
    const int wid = tid >> 5, lane = tid & 31;
    const uint32_t sbase = smem_u32(smem);
    const int bid = blockIdx.x;
    const bool want_hf = (out_size >= (int)((size_t)S_ * BH_ + LBH_));
    float dh[2][4][4], dl[2][4][4];

    // ---- phase A: P = X @ W_xh + b_h ----
    for (int u = bid; u < 4096; u += NB) {
        int s = u >> 3, m = u & 7;
        ZACC();
        const char* Ah = (const char*)g_Whi + ((size_t)2560 + m * 16) * 4096;
        const char* Al = (const char*)g_Wlo + ((size_t)2560 + m * 16) * 4096;
        const char* Bf = (const char*)g_Xf + (size_t)s * 16 * 2048;
        gemm_pipe(Ah, Al, Bf, smem, sbase, 0, 8, dh, dl, tid, wid, lane);
        stage_D(smem, dh, dl, wid, lane);
        __syncthreads();
        {
            int b = tid >> 2, seg = tid & 3;
            float* Ps = g_P + (size_t)s * BH_ + (size_t)b * H_ + m * 128;
            const float* st = (const float*)smem;
#pragma unroll
            for (int i = 0; i < 8; ++i) {
                int ff = (seg + 4 * i) * 4;
                float4 v = *(const float4*)(st + b * 132 + ff);
                float4 bb = *(const float4*)(b_h + m * 128 + ff);
                v.x += bb.x; v.y += bb.y; v.z += bb.z; v.w += bb.w;
                *(float4*)(Ps + ff) = v;
            }
        }
        __syncthreads();
    }
    grid_sync(NB);

    // ---- phase B: recurrence ----
    const int unit = bid / 3, ks = bid - unit * 3;
    const int gmat = unit >> 3, m = unit & 7;
    const int layer = (gmat == 0) ? 0 : ((gmat <= 2) ? 1 : 2);
    const int srcL = (gmat == 0) ? 0 : (gmat == 1) ? 1 : (gmat == 2) ? 0 : (gmat == 3) ? 2 : 1;
    const int c0 = ks * 11, c1 = (ks == 2) ? 32 : c0 + 11;
    const char* Ah = (const char*)g_Whi + (size_t)(gmat * 8 + m) * 64 * 4096;
    const char* Al = (const char*)g_Wlo + (size_t)(gmat * 8 + m) * 64 * 4096;
    const int tile = layer * 8 + m;
    const int gs = layer ? 6 : 3;
    const int rank = ks + ((layer && (gmat == 2 || gmat == 4)) ? 3 : 0);
    const int r0 = (64 * rank) / gs, r1 = (64 * (rank + 1)) / gs;
    const float* pa = g_part + (size_t)(((layer == 0 ? 0 : (layer == 1 ? 1 : 3)) * 8 + m) * 3) * 8192;
    const float* pb = g_part + (size_t)(((layer == 1 ? 2 : 4) * 8 + m) * 3) * 8192;
    const int f = tid & 127, mf = m * 128 + f;
    const float bias = layer ? bL[(layer - 1) * H_ + mf] : 0.0f;

    for (int s = 0; s < S_; ++s) {
        const char* Bf = (const char*)g_hf + (size_t)(s & 1) * LBH_ * 2 + (size_t)srcL * 64 * 2048;
        ZACC();
        gemm_pipe(Ah, Al, Bf, smem, sbase, c0, c1, dh, dl, tid, wid, lane);
        stage_D(smem, dh, dl, wid, lane);
        __syncthreads();
        {
            int b = tid >> 2, seg = tid & 3;
            float* pp = g_part + (size_t)bid * 8192 + b * 128;
            const float* st = (const float*)smem;
#pragma unroll
            for (int i = 0; i < 8; ++i) {
                int ff = (seg + 4 * i) * 4;
                *(float4*)(pp + ff) = *(const float4*)(st + b * 132 + ff);
            }
        }
        __syncthreads();
        if (tid == 0) {
            __threadfence();
            atomicAdd(&g_flag[tile], 1u);
            unsigned tgt = (unsigned)gs * (unsigned)(s + 1);
            while (*(volatile unsigned*)&g_flag[tile] < tgt) { }
        }
        __syncthreads();
        __threadfence();
        {
            const size_t wrE = (size_t)((s & 1) ^ 1) * LBH_;
            __half* dst = g_hf + wrE + ((size_t)layer * 64 + (mf >> 4)) * 1024;
            float* os = out + (size_t)s * BH_;
            for (int b = r0 + (tid >> 7); b < r1; b += 2) {
                int idx = b * 128 + f;
                float v = bias + pa[idx] + pa[8192 + idx] + pa[16384 + idx];
                if (layer) v += pb[idx] + pb[8192 + idx] + pb[16384 + idx];
                else       v += g_P[(size_t)s * BH_ + (size_t)b * H_ + mf];
                float o = tanhf(v);
                dst[rowoff(b, mf & 15)] = __float2half(o);
                if (layer == 2) os[(size_t)b * H_ + mf] = o;
                if (s == S_ - 1 && want_hf)
                    out[(size_t)S_ * BH_ + (size_t)layer * BH_ + (size_t)b * H_ + mf] = o;
            }
        }
        grid_sync(NB);
    }
}

extern "C" void kernel_launch(void* const* d_in, const int* in_sizes, int n_in,
                              void* d_out, int out_size) {
    const float* X    = (const float*)d_in[0];
    const float* W_xh = (const float*)d_in[1];
    const float* W_hh = (const float*)d_in[2];
    const float* b_h  = (const float*)d_in[3];
    const float* W_l  = (const float*)d_in[4];
    const float* U_l  = (const float*)d_in[5];
    const float* b_l  = (const float*)d_in[6];
    float* out = (float*)d_out;

    cudaFuncSetAttribute(k_main, cudaFuncAttributeMaxDynamicSharedMemorySize, SMEM_DYN);
    k_init<<<768, 256>>>();
    k_prepw<<<20480, 256>>>(W_hh, W_l, U_l);
    k_prepxh<<<1024, 256>>>(W_xh);
    k_prepx<<<32768, 256>>>(X);
    k_main<<<NB, 256, SMEM_DYN>>>(b_h, b_l, out, out_size);
}

// round 10
// speedup vs baseline: 5.1795x; 1.0359x over previous
#include <cuda_runtime.h>
#include <cuda_fp16.h>
#include <math.h>
#include <stdint.h>

#define S_ 512
#define B_ 64
#define I_ 256
#define H_ 1024
#define BH_ 65536
#define LBH_ 196608
#define NB 120
#define SLOT 20480          // phase-A pipeline slot
#define BOFF 180224         // phase-B: B region / stage scratch
#define SMEM_DYN 225280
#define LOSCALE 2048.0f
#define ILOSCALE (1.0f / 2048.0f)

// ---------------- static device scratch ----------------
__device__ __align__(16) float g_P[(size_t)S_ * BH_];
__device__ __align__(16) __half g_Whi[2688 * 2048];   // 5 mats + Wxh, blocked K16 x 8 mtiles
__device__ __align__(16) __half g_Wlo[2688 * 2048];   // lo plane, pre-scaled by 2^11
__device__ __align__(16) __half g_Xf[8192 * 1024];    // X fp16, blocked
__device__ __align__(16) __half g_hf[2 * LBH_];       // h fp16, double-buffered
__device__ __align__(16) float g_part[2 * NB * 8192]; // partials, parity double-buffered
__device__ unsigned g_pdone[24 * 32];                 // per-tile partial-write counters (padded)
__device__ unsigned g_hready[3 * 32];                 // per-layer h-written counters
__device__ unsigned g_hused[3 * 32];                  // per-layer h-read counters
__device__ unsigned g_cnt;
__device__ volatile unsigned g_gen;

__constant__ int c_inc[3]  = {24, 48, 48};            // epilogue CTAs per layer per step
__constant__ int c_cons[3] = {48, 48, 24};            // B-consumer CTAs per layer per step

// blocked-row element index with XOR swizzle (bank-conflict-free fragment loads)
__device__ __forceinline__ uint32_t rowoff(int r, int j) {
    int w = j >> 1;
    return (uint32_t)(r * 16 + (((w ^ (r & 4)) << 1) | (j & 1)));
}

// ---------------- PTX helpers ----------------
__device__ __forceinline__ uint32_t smem_u32(const void* p) {
    uint32_t a;
    asm("{ .reg .u64 t; cvta.to.shared.u64 t, %1; cvt.u32.u64 %0, t; }" : "=r"(a) : "l"(p));
    return a;
}
__device__ __forceinline__ void cp16(uint32_t s, const void* g) {
    asm volatile("cp.async.cg.shared.global [%0], [%1], 16;" :: "r"(s), "l"(g) : "memory");
}
__device__ __forceinline__ void cp_commit() { asm volatile("cp.async.commit_group;" ::: "memory"); }
__device__ __forceinline__ void cp_wait2()  { asm volatile("cp.async.wait_group 2;" ::: "memory"); }
__device__ __forceinline__ void cp_wait0()  { asm volatile("cp.async.wait_group 0;" ::: "memory"); }

__device__ __forceinline__ void mmaf16(float* d, uint32_t a0, uint32_t a1, uint32_t a2,
                                       uint32_t a3, uint32_t b0, uint32_t b1) {
    asm volatile(
        "mma.sync.aligned.m16n8k16.row.col.f32.f16.f16.f32 "
        "{%0,%1,%2,%3}, {%4,%5,%6,%7}, {%8,%9}, {%0,%1,%2,%3};"
        : "+f"(d[0]), "+f"(d[1]), "+f"(d[2]), "+f"(d[3])
        : "r"(a0), "r"(a1), "r"(a2), "r"(a3), "r"(b0), "r"(b1));
}

__device__ __forceinline__ void grid_sync(unsigned nb) {
    __syncthreads();
    if (threadIdx.x == 0) {
        __threadfence();
        unsigned g = g_gen;
        if (atomicAdd(&g_cnt, 1u) == nb - 1u) {
            g_cnt = 0;
            __threadfence();
            g_gen = g + 1u;
        } else {
            while (g_gen == g) { }
        }
    }
    __syncthreads();
}

__device__ __forceinline__ void spin_ge(unsigned* ctr, unsigned tgt) {
    while (*(volatile unsigned*)ctr < tgt) { }
}

// ---------------- prep kernels ----------------
__global__ void k_init() {
    int i = blockIdx.x * blockDim.x + threadIdx.x;
    uint32_t* a = (uint32_t*)g_hf;
    if (i < 196608) a[i] = 0u;
    if (i < 24 * 32) g_pdone[i] = 0u;
    if (i < 3 * 32) { g_hready[i] = 0u; g_hused[i] = 0u; }
}
__device__ __forceinline__ void wsplit(float v, size_t e) {
    __half hi = __float2half(v);
    g_Whi[e] = hi;
    g_Wlo[e] = __float2half((v - __half2float(hi)) * LOSCALE);
}
__global__ void k_prepw(const float* __restrict__ Whh, const float* __restrict__ Wl,
                        const float* __restrict__ Ul) {
    int idx = blockIdx.x * blockDim.x + threadIdx.x;
    if (idx >= 5 * 1024 * 1024) return;
    int g = idx >> 20, rem = idx & 1048575, k = rem >> 10, f = rem & 1023;
    float v;
    if (g == 0)      v = Whh[(size_t)k * H_ + f];
    else if (g == 1) v = Ul[(size_t)k * H_ + f];
    else if (g == 2) v = Wl[(size_t)k * H_ + f];
    else if (g == 3) v = Ul[(size_t)H_ * H_ + (size_t)k * H_ + f];
    else             v = Wl[(size_t)H_ * H_ + (size_t)k * H_ + f];
    size_t blk = (size_t)(g * 8 + (f >> 7)) * 64 + (k >> 4);
    wsplit(v, blk * 2048 + rowoff(f & 127, k & 15));
}
__global__ void k_prepxh(const float* __restrict__ Wxh) {
    int idx = blockIdx.x * blockDim.x + threadIdx.x;
    if (idx >= 256 * 1024) return;
    int k = idx >> 10, f = idx & 1023;
    size_t blk = 2560 + (size_t)(f >> 7) * 16 + (k >> 4);
    wsplit(Wxh[(size_t)k * H_ + f], blk * 2048 + rowoff(f & 127, k & 15));
}
__global__ void k_prepx(const float* __restrict__ X) {
    int idx = blockIdx.x * blockDim.x + threadIdx.x;
    if (idx >= S_ * B_ * I_) return;
    int s = idx >> 14, b = (idx >> 8) & 63, i = idx & 255;
    g_Xf[((size_t)s * 16 + (i >> 4)) * 1024 + rowoff(b, i & 15)] = __float2half(X[idx]);
}

// ---------------- GEMM core ----------------
__device__ __forceinline__ void sub_iter(const char* Ah, const char* Al, const char* Bf,
                                         int wid, int lane, float dh[2][4][4], float dl[2][4][4]) {
    const int g = lane >> 2, t = lane & 3;
    const int fr = (wid >> 1) * 32, nb = (wid & 1) * 32;
    const int sw = g & 4;
    uint32_t ah[2][4], al[2][4], bb[4][2];
#pragma unroll
    for (int mt = 0; mt < 2; ++mt) {
        int r0 = fr + mt * 16 + g;
        uint32_t o0 = (uint32_t)(r0 * 32 + ((t ^ sw) << 2));
        uint32_t o2 = (uint32_t)(r0 * 32 + (((t + 4) ^ sw) << 2));
        ah[mt][0] = *(const uint32_t*)(Ah + o0);
        ah[mt][1] = *(const uint32_t*)(Ah + o0 + 256);
        ah[mt][2] = *(const uint32_t*)(Ah + o2);
        ah[mt][3] = *(const uint32_t*)(Ah + o2 + 256);
        al[mt][0] = *(const uint32_t*)(Al + o0);
        al[mt][1] = *(const uint32_t*)(Al + o0 + 256);
        al[mt][2] = *(const uint32_t*)(Al + o2);
        al[mt][3] = *(const uint32_t*)(Al + o2 + 256);
    }
#pragma unroll
    for (int nt = 0; nt < 4; ++nt) {
        int rb = nb + nt * 8 + g;
        uint32_t o0 = (uint32_t)(rb * 32 + ((t ^ sw) << 2));
        uint32_t o1 = (uint32_t)(rb * 32 + (((t + 4) ^ sw) << 2));
        bb[nt][0] = *(const uint32_t*)(Bf + o0);
        bb[nt][1] = *(const uint32_t*)(Bf + o1);
    }
#pragma unroll
    for (int mt = 0; mt < 2; ++mt)
#pragma unroll
        for (int nt = 0; nt < 4; ++nt) {
            mmaf16(dh[mt][nt], ah[mt][0], ah[mt][1], ah[mt][2], ah[mt][3], bb[nt][0], bb[nt][1]);
            mmaf16(dl[mt][nt], al[mt][0], al[mt][1], al[mt][2], al[mt][3], bb[nt][0], bb[nt][1]);
        }
}

// phase-A streaming pipeline (weights not resident for Wxh GEMM)
__device__ __forceinline__ void load_chunkA(uint32_t so, const char* Ah, const char* Al,
                                            const char* Bf, int c, int tid) {
    size_t ao = (size_t)c * 8192 + tid * 16;
    cp16(so + tid * 16, Ah + ao);
    cp16(so + 4096 + tid * 16, Ah + ao + 4096);
    cp16(so + 8192 + tid * 16, Al + ao);
    cp16(so + 12288 + tid * 16, Al + ao + 4096);
    cp16(so + 16384 + tid * 16, Bf + (size_t)c * 4096 + tid * 16);
}
__device__ __forceinline__ void gemm_pipeA(const char* Ah, const char* Al, const char* Bf,
                                           const char* sm, uint32_t sbase,
                                           float dh[2][4][4], float dl[2][4][4],
                                           int tid, int wid, int lane) {
#pragma unroll
    for (int i = 0; i < 3; ++i) {
        load_chunkA(sbase + i * SLOT, Ah, Al, Bf, i, tid);
        cp_commit();
    }
    for (int c = 0; c < 8; ++c) {
        const int slot = c & 3;
        cp_wait2();
        __syncthreads();
        if (c + 3 < 8) load_chunkA(sbase + ((c + 3) & 3) * SLOT, Ah, Al, Bf, c + 3, tid);
        cp_commit();
        const char* p = sm + slot * SLOT;
        sub_iter(p, p + 8192, p + 16384, wid, lane, dh, dl);
        sub_iter(p + 4096, p + 12288, p + 18432, wid, lane, dh, dl);
    }
    cp_wait0();
    __syncthreads();
}

__device__ __forceinline__ void stage_D(float* st, float dh[2][4][4], float dl[2][4][4],
                                        int wid, int lane) {
    const int g = lane >> 2, t = lane & 3;
    const int fr = (wid >> 1) * 32, nb = (wid & 1) * 32;
#pragma unroll
    for (int mt = 0; mt < 2; ++mt)
#pragma unroll
        for (int nt = 0; nt < 4; ++nt) {
            int f0 = fr + mt * 16 + g, b0 = nb + nt * 8 + 2 * t;
            st[b0 * 132 + f0]           = dh[mt][nt][0] + dl[mt][nt][0] * ILOSCALE;
            st[(b0 + 1) * 132 + f0]     = dh[mt][nt][1] + dl[mt][nt][1] * ILOSCALE;
            st[b0 * 132 + f0 + 8]       = dh[mt][nt][2] + dl[mt][nt][2] * ILOSCALE;
            st[(b0 + 1) * 132 + f0 + 8] = dh[mt][nt][3] + dl[mt][nt][3] * ILOSCALE;
        }
}

#define ZACC()                                        \
    do {                                              \
        _Pragma("unroll") for (int a_ = 0; a_ < 2; ++a_) \
        _Pragma("unroll") for (int b_ = 0; b_ < 4; ++b_) \
        _Pragma("unroll") for (int c_ = 0; c_ < 4; ++c_) \
        { dh[a_][b_][c_] = 0.0f; dl[a_][b_][c_] = 0.0f; } \
    } while (0)

// ---------------- main persistent kernel (120 CTAs, dataflow-synced) ----------------
__global__ void __launch_bounds__(256, 1) k_main(const float* __restrict__ b_h,
                                                 const float* __restrict__ bL,
                                                 float* __restrict__ out, int out_size) {
    extern __shared__ __align__(16) char smem[];
    const int tid = threadIdx.x;
    const int wid = tid >> 5, lane = tid & 31;
    const uint32_t sbase = smem_u32(smem);
    const int bid = blockIdx.x;
    const bool want_hf = (out_size >= (int)((size_t)S_ * BH_ + LBH_));
    float dh[2][4][4], dl[2][4][4];

    // ---- phase A: P = X @ W_xh + b_h (streamed pipeline) ----
    for (int u = bid; u < 4096; u += NB) {
        int s = u >> 3, m = u & 7;
        ZACC();
        const char* Ah = (const char*)g_Whi + ((size_t)2560 + m * 16) * 4096;
        const char* Al = (const char*)g_Wlo + ((size_t)2560 + m * 16) * 4096;
        const char* Bf = (const char*)g_Xf + (size_t)s * 16 * 2048;
        gemm_pipeA(Ah, Al, Bf, smem, sbase, dh, dl, tid, wid, lane);
        stage_D((float*)smem, dh, dl, wid, lane);
        __syncthreads();
        {
            int b = tid >> 2, seg = tid & 3;
            float* Ps = g_P + (size_t)s * BH_ + (size_t)b * H_ + m * 128;
            const float* st = (const float*)smem;
#pragma unroll
            for (int i = 0; i < 8; ++i) {
                int ff = (seg + 4 * i) * 4;
                float4 v = *(const float4*)(st + b * 132 + ff);
                float4 bb = *(const float4*)(b_h + m * 128 + ff);
                v.x += bb.x; v.y += bb.y; v.z += bb.z; v.w += bb.w;
                *(float4*)(Ps + ff) = v;
            }
        }
        __syncthreads();
    }
    grid_sync(NB);

    // ---- phase B setup ----
    const int unit = bid / 3, ks = bid - unit * 3;
    const int gmat = unit >> 3, m = unit & 7;
    const int layer = (gmat == 0) ? 0 : ((gmat <= 2) ? 1 : 2);
    const int srcL = (gmat == 0) ? 0 : (gmat == 1) ? 1 : (gmat == 2) ? 0 : (gmat == 3) ? 2 : 1;
    const int c0 = ks * 11, c1 = (ks == 2) ? 32 : c0 + 11;
    const int nch = c1 - c0;
    const int tile = layer * 8 + m;
    const int gs = layer ? 6 : 3;
    const int rank = ks + ((layer && (gmat == 2 || gmat == 4)) ? 3 : 0);
    const int r0 = (64 * rank) / gs, r1 = (64 * (rank + 1)) / gs;
    const int f = tid & 127, mf = m * 128 + f;
    const float bias = layer ? bL[(layer - 1) * H_ + mf] : 0.0f;

    // load resident weight slice into SMEM (once)
    {
        const char* gh = (const char*)g_Whi + (size_t)(gmat * 8 + m) * 64 * 4096;
        const char* gl = (const char*)g_Wlo + (size_t)(gmat * 8 + m) * 64 * 4096;
        for (int c = 0; c < nch; ++c) {
            size_t gg = (size_t)(c0 + c) * 8192 + tid * 16;
            uint32_t so = sbase + c * 16384 + tid * 16;
            cp16(so, gh + gg);
            cp16(so + 4096, gh + gg + 4096);
            cp16(so + 8192, gl + gg);
            cp16(so + 12288, gl + gg + 4096);
        }
        cp_commit();
        cp_wait0();
        __syncthreads();
    }

    // ---- phase B: recurrence (no global barriers) ----
    for (int s = 0; s < S_; ++s) {
        // wait h(srcL) state s ready, then load B
        if (tid == 0) {
            spin_ge(&g_hready[srcL * 32], (unsigned)c_inc[srcL] * (unsigned)s);
            __threadfence();
        }
        __syncthreads();
        {
            const char* hb = (const char*)(g_hf + (size_t)(s & 1) * LBH_ + (size_t)srcL * 65536);
            for (int c = 0; c < nch; ++c)
                cp16(sbase + BOFF + c * 4096 + tid * 16, hb + (size_t)(c0 + c) * 4096 + tid * 16);
            cp_commit();
            cp_wait0();
            __syncthreads();
        }
        if (tid == 0) { __threadfence(); atomicAdd(&g_hused[srcL * 32], 1u); }

        // compute (resident weights, resident B, no syncs)
        ZACC();
        for (int c = 0; c < nch; ++c) {
            const char* pA = smem + c * 16384;
            const char* pB = smem + BOFF + c * 4096;
            sub_iter(pA, pA + 8192, pB, wid, lane, dh, dl);
            sub_iter(pA + 4096, pA + 12288, pB + 2048, wid, lane, dh, dl);
        }
        __syncthreads();                       // B region dead; reuse as stage scratch
        stage_D((float*)(smem + BOFF), dh, dl, wid, lane);
        __syncthreads();

        // write partials (parity-buffered), signal pdone, wait peers + hused
        float* pbase = g_part + (size_t)(s & 1) * NB * 8192;
        {
            int b = tid >> 2, seg = tid & 3;
            float* pp = pbase + (size_t)bid * 8192 + b * 128;
            const float* st = (const float*)(smem + BOFF);
#pragma unroll
            for (int i = 0; i < 8; ++i) {
                int ff = (seg + 4 * i) * 4;
                *(float4*)(pp + ff) = *(const float4*)(st + b * 132 + ff);
            }
        }
        __threadfence();
        __syncthreads();
        if (tid == 0) {
            atomicAdd(&g_pdone[tile * 32], 1u);
            spin_ge(&g_pdone[tile * 32], (unsigned)gs * (unsigned)(s + 1));
            spin_ge(&g_hused[layer * 32], (unsigned)c_cons[layer] * (unsigned)s);
            __threadfence();
        }
        __syncthreads();

        // epilogue: combine partials, tanh, write h(+out), signal hready
        {
            const float* pa = pbase + (size_t)(((layer == 0 ? 0 : (layer == 1 ? 1 : 3)) * 8 + m) * 3) * 8192;
            const float* pb2 = pbase + (size_t)(((layer == 1 ? 2 : 4) * 8 + m) * 3) * 8192;
            const size_t wrE = (size_t)((s & 1) ^ 1) * LBH_;
            __half* dst = g_hf + wrE + ((size_t)layer * 64 + (mf >> 4)) * 1024;
            float* os = out + (size_t)s * BH_;
            for (int b = r0 + (tid >> 7); b < r1; b += 2) {
                int idx = b * 128 + f;
                float v = bias + pa[idx] + pa[8192 + idx] + pa[16384 + idx];
                if (layer) v += pb2[idx] + pb2[8192 + idx] + pb2[16384 + idx];
                else       v += g_P[(size_t)s * BH_ + (size_t)b * H_ + mf];
                float o = tanhf(v);
                dst[rowoff(b, mf & 15)] = __float2half(o);
                if (layer == 2) os[(size_t)b * H_ + mf] = o;
                if (s == S_ - 1 && want_hf)
                    out[(size_t)S_ * BH_ + (size_t)layer * BH_ + (size_t)b * H_ + mf] = o;
            }
        }
        __threadfence();
        __syncthreads();
        if (tid == 0) atomicAdd(&g_hready[layer * 32], 1u);
    }
}

extern "C" void kernel_launch(void* const* d_in, const int* in_sizes, int n_in,
                              void* d_out, int out_size) {
    const float* X    = (const float*)d_in[0];
    const float* W_xh = (const float*)d_in[1];
    const float* W_hh = (const float*)d_in[2];
    const float* b_h  = (const float*)d_in[3];
    const float* W_l  = (const float*)d_in[4];
    const float* U_l  = (const float*)d_in[5];
    const float* b_l  = (const float*)d_in[6];
    float* out = (float*)d_out;

    cudaFuncSetAttribute(k_main, cudaFuncAttributeMaxDynamicSharedMemorySize, SMEM_DYN);
    k_init<<<768, 256>>>();
    k_prepw<<<20480, 256>>>(W_hh, W_l, U_l);
    k_prepxh<<<1024, 256>>>(W_xh);
    k_prepx<<<32768, 256>>>(X);
    k_main<<<NB, 256, SMEM_DYN>>>(b_h, b_l, out, out_size);
}